// round 7
// baseline (speedup 1.0000x reference)
#include <cuda_runtime.h>
#include <stdint.h>

// MeanAggregator: out[b, :] = mean over {neighbours[b,0..9], nodes[b]} of features[idx, :]
// B = 100000, K = 10, N = 1000000, D = 128 (fp32). Indices int32 (JAX x64 disabled).
//
// D-split (4 quarters of 32 floats): per-pass distinct-row footprint 667k x 128 B = 85 MB
// < L2 (126 MB) -> repeat refs hit L2 (verified: ~414 MB DRAM, the compulsory floor).
// Warp handles 4 (row, quarter) pairs: 4 subgroups of 8 lanes, lane = float4 slot,
// so every gather is a coalesced LDG.128.
//
// R7 change: gathers split into 6+5 batches to cut live regs (44 -> 24 float4 regs),
// launch_bounds(256,6) caps regs at 42 -> 6 CTAs/SM (48 warps) for the concurrency
// needed now that ~40% of refs are fast L2 hits.

#define B_NODES   100000
#define K_NEIGH   10
#define D_DIM     128
#define D_VEC     (D_DIM / 4)    // 32 float4 per row
#define Q_VEC     8              // 8 float4 per quarter
#define BATCH1    6
#define BATCH2    5              // BATCH1 + BATCH2 = K_NEIGH + 1

__global__ __launch_bounds__(256, 6)
void mean_agg_kernel(const int*    __restrict__ nodes,
                     const int*    __restrict__ neighbours,
                     const float4* __restrict__ features,
                     float4*       __restrict__ out)
{
    const int warp = (blockIdx.x * blockDim.x + threadIdx.x) >> 5;  // 0..24999
    const int lane = threadIdx.x & 31;
    const int sub  = lane >> 3;        // subgroup 0..3 -> row offset
    const int sl   = lane & 7;         // float4 slot within quarter
    const int q    = blockIdx.y;       // feature-dim quarter (slowest-varying)

    const int row = warp * 4 + sub;
    if (row >= B_NODES) return;

    // 11 row indices for this subgroup's row (converged within subgroup).
    int idx[K_NEIGH + 1];
#pragma unroll
    for (int k = 0; k < K_NEIGH; ++k)
        idx[k] = __ldcs(&neighbours[row * K_NEIGH + k]);
    idx[K_NEIGH] = __ldcs(&nodes[row]);

    const float4* fq = features + q * Q_VEC + sl;

    float4 acc = make_float4(0.f, 0.f, 0.f, 0.f);

    // Batch 1: 6 independent LDG.128 gathers in flight.
    {
        float4 v[BATCH1];
#pragma unroll
        for (int k = 0; k < BATCH1; ++k)
            v[k] = __ldg(fq + (long long)idx[k] * D_VEC);
#pragma unroll
        for (int k = 0; k < BATCH1; ++k) {
            acc.x += v[k].x; acc.y += v[k].y;
            acc.z += v[k].z; acc.w += v[k].w;
        }
    }

    // Batch 2: remaining 5 gathers.
    {
        float4 v[BATCH2];
#pragma unroll
        for (int k = 0; k < BATCH2; ++k)
            v[k] = __ldg(fq + (long long)idx[BATCH1 + k] * D_VEC);
#pragma unroll
        for (int k = 0; k < BATCH2; ++k) {
            acc.x += v[k].x; acc.y += v[k].y;
            acc.z += v[k].z; acc.w += v[k].w;
        }
    }

    const float s = 1.0f / (float)(K_NEIGH + 1);
    acc.x *= s; acc.y *= s; acc.z *= s; acc.w *= s;

    __stcs(&out[(long long)row * D_VEC + q * Q_VEC + sl], acc);
}

extern "C" void kernel_launch(void* const* d_in, const int* in_sizes, int n_in,
                              void* d_out, int out_size)
{
    const int*    nodes      = (const int*)d_in[0];
    const int*    neighbours = (const int*)d_in[1];
    const float4* features   = (const float4*)d_in[2];
    float4*       out        = (float4*)d_out;

    const int threads = 256;
    const int warps_needed = (B_NODES + 3) / 4;                       // 25000
    dim3 grid((warps_needed * 32 + threads - 1) / threads, 4);        // 3125 x 4
    mean_agg_kernel<<<grid, threads>>>(nodes, neighbours, features, out);
}